// round 14
// baseline (speedup 1.0000x reference)
#include <cuda_runtime.h>
#include <cuda_fp16.h>
#include <cstdint>
#include <math.h>

#define B_    8192
#define DIN_  1024
#define DH_   2048
#define DOUT_ 1024
#define NE_   8
#define TAU_  0.8f
#define LAMB_ 0.05f

// block 128x128, 8 warps (4x2), warp tile 32x64, BK=32 halves, 7 stages, 2 CTAs/SM
// ktiles processed in PAIRS: one wait+sync per 2 ktiles. Warp-group ks stagger.
#define BM 128
#define BN 128
#define BK 32
#define NT 256
#define STAGES 7
#define A_BYTES (BM * BK * 2)         // 8192
#define B_BYTES (BK * BN * 2)         // 8192
#define STG_BYTES (A_BYTES + B_BYTES) // 16384
#define SMEM_BYTES (STAGES * STG_BYTES)  // 114688
#define KSPLIT 4

// -------- scratch (__device__ globals; 16B-aligned via uint4) --------
__device__ float g_probs[(size_t)B_ * NE_];
__device__ float g_sums[16];
__device__ uint4 g_xh4[(size_t)B_ * DIN_ / 8];
__device__ uint4 g_w1h4[(size_t)NE_ * DIN_ * DH_ / 8];
__device__ uint4 g_w2h4[(size_t)NE_ * DH_ * DOUT_ / 8];
__device__ uint4 g_hp4[(size_t)B_ * NE_ * DH_ / 8];       // fp16 h' [B][E*Dh]
__device__ uint4 g_part16[(size_t)KSPLIT * B_ * DOUT_ / 8]; // fp16 split-K partials

// ---------------- helpers ----------------
__device__ __forceinline__ uint32_t smem_u32(const void* p) {
    uint32_t a;
    asm("{ .reg .u64 t; cvta.to.shared.u64 t, %1; cvt.u32.u64 %0, t; }" : "=r"(a) : "l"(p));
    return a;
}
__device__ __forceinline__ void cpa16(uint32_t dst, const void* src) {
    asm volatile("cp.async.cg.shared.global [%0], [%1], 16;" :: "r"(dst), "l"(src));
}
#define CP_COMMIT() asm volatile("cp.async.commit_group;" ::: "memory")
#define CP_WAIT3()  asm volatile("cp.async.wait_group 3;" ::: "memory")

__device__ __forceinline__ void ldsm4(uint32_t* r, uint32_t addr) {
    asm volatile("ldmatrix.sync.aligned.m8n8.x4.shared.b16 {%0,%1,%2,%3}, [%4];"
        : "=r"(r[0]), "=r"(r[1]), "=r"(r[2]), "=r"(r[3]) : "r"(addr));
}
__device__ __forceinline__ void ldsm4t(uint32_t* r, uint32_t addr) {
    asm volatile("ldmatrix.sync.aligned.m8n8.x4.trans.shared.b16 {%0,%1,%2,%3}, [%4];"
        : "=r"(r[0]), "=r"(r[1]), "=r"(r[2]), "=r"(r[3]) : "r"(addr));
}
__device__ __forceinline__ void mma16(float* c, const uint32_t* a, const uint32_t* b) {
    asm volatile(
        "mma.sync.aligned.m16n8k16.row.col.f32.f16.f16.f32 "
        "{%0,%1,%2,%3},{%4,%5,%6,%7},{%8,%9},{%0,%1,%2,%3};"
        : "+f"(c[0]), "+f"(c[1]), "+f"(c[2]), "+f"(c[3])
        : "r"(a[0]), "r"(a[1]), "r"(a[2]), "r"(a[3]), "r"(b[0]), "r"(b[1]));
}

// ---------------- prep: fp32 -> fp16 (w1, w2; x handled in gate) ----------------
__global__ __launch_bounds__(256) void half_kernel(const float* __restrict__ s1,
                                                   __half* __restrict__ d1, int n1_,
                                                   const float* __restrict__ s2,
                                                   __half* __restrict__ d2, int n2_) {
    int stride = gridDim.x * 256;
    int t0 = blockIdx.x * 256 + threadIdx.x;
    for (int i = t0; i < n1_; i += stride) {
        float4 v = ((const float4*)s1)[i];
        ((__half2*)d1)[2 * i]     = __floats2half2_rn(v.x, v.y);
        ((__half2*)d1)[2 * i + 1] = __floats2half2_rn(v.z, v.w);
    }
    for (int i = t0; i < n2_; i += stride) {
        float4 v = ((const float4*)s2)[i];
        ((__half2*)d2)[2 * i]     = __floats2half2_rn(v.x, v.y);
        ((__half2*)d2)[2 * i + 1] = __floats2half2_rn(v.z, v.w);
    }
}

// ---------------- main GEMM (fp16 in, fp32 accum), 256 threads, 2 CTAs/SM ----------------
// MODE 1: h' = fp16(probs * relu(xh @ w1h + b1)), grid.z = expert, KT=32
// MODE 2: part16[kq] = fp16(hp slice @ w2h slice), grid.z = kq, KT=128
template <int MODE>
__global__ __launch_bounds__(NT, 2) void gemm_h(const __half* __restrict__ Aglob,
                                                const __half* __restrict__ Bglob,
                                                const float* __restrict__ bias) {
    constexpr int KT  = (MODE == 1) ? (DIN_ / BK) : (NE_ * DH_ / BK / KSPLIT);
    constexpr int LDA = (MODE == 1) ? DIN_ : (NE_ * DH_);
    constexpr int LDB = (MODE == 1) ? DH_ : DOUT_;

    extern __shared__ float sm[];
    const int tid  = threadIdx.x;
    const int lane = tid & 31, warp = tid >> 5;
    const int g = lane >> 2, t = lane & 3;
    const int wm = warp >> 1, wn = warp & 1;     // 4x2 warps, warp tile 32x64
    const int sw = (warp >> 2) & 1;              // ks-stagger group (anti-phase per SMSP)

    const int e  = blockIdx.z;                   // expert (MODE1) or kq (MODE2)
    const int m0 = blockIdx.y * BM;
    const int n0 = blockIdx.x * BN;
    const __half* hp = (const __half*)g_hp4;
    const __half* Ap = (MODE == 1) ? (Aglob + (size_t)m0 * LDA)
                                   : (hp + (size_t)m0 * LDA + (size_t)e * (NE_ * DH_ / KSPLIT));
    const __half* Bp = (MODE == 1)
        ? (Bglob + (size_t)e * DIN_ * DH_ + n0)
        : (Bglob + (size_t)e * (NE_ * DH_ / KSPLIT) * LDB + n0);
    const uint32_t sbase = smem_u32(sm);

    // copy descriptors: A 512 chunks (2/thr), B 512 chunks (2/thr)
    const __half* pA[2]; uint32_t soA[2];
    const __half* pB[2]; uint32_t soB[2];
#pragma unroll
    for (int j = 0; j < 2; j++) {
        int id = tid + j * NT, m = id >> 2, c = id & 3;
        pA[j]  = Ap + (size_t)m * LDA + c * 8;
        soA[j] = (uint32_t)(((m >> 1) << 3) + ((((m & 1) << 2) | c) ^ ((m >> 1) & 7))) * 16;
    }
#pragma unroll
    for (int j = 0; j < 2; j++) {
        int id = tid + j * NT, k = id >> 4, cn = id & 15;
        pB[j]  = Bp + (size_t)k * LDB + cn * 8;
        soB[j] = (uint32_t)(A_BYTES) + (uint32_t)(k * 16 + (cn ^ (k & 7))) * 16;
    }

    auto issue = [&](uint32_t stg) {
#pragma unroll
        for (int j = 0; j < 2; j++) { cpa16(stg + soA[j], pA[j]); pA[j] += BK; }
#pragma unroll
        for (int j = 0; j < 2; j++) { cpa16(stg + soB[j], pB[j]); pB[j] += (size_t)BK * LDB; }
    };

    float acc[2][8][4];
#pragma unroll
    for (int a = 0; a < 2; a++)
#pragma unroll
        for (int b = 0; b < 8; b++)
#pragma unroll
            for (int c = 0; c < 4; c++) acc[a][b][c] = 0.f;

    // prologue: 5 stages in flight
#pragma unroll
    for (int p = 0; p < 5; p++) { issue(sbase + p * STG_BYTES); CP_COMMIT(); }

    // ldmatrix per-lane precomputes
    const int mat = lane >> 3, mr = lane & 7;
    const int matc = mat >> 1, matm = (mat & 1) << 3;
    uint32_t a_b8[2], a_e[2], a_hm[2];
#pragma unroll
    for (int mt = 0; mt < 2; mt++) {
        int m = wm * 32 + mt * 16 + matm + mr;
        a_b8[mt] = (uint32_t)((m >> 1) << 3);
        a_e[mt]  = (uint32_t)((m >> 1) & 7);
        a_hm[mt] = (uint32_t)((m & 1) << 2);
    }
    uint32_t b_cb[4];
#pragma unroll
    for (int ntp = 0; ntp < 4; ntp++) {
        int kb = matm + mr;                    // row within 16-row half-tile
        int cn = wn * 8 + ntp * 2 + matc;      // chunk-in-row
        b_cb[ntp] = (uint32_t)(kb * 16 + (cn ^ mr)) * 16;
    }

    uint32_t aF[2][4], bF[8][2];
    auto load_frag = [&](uint32_t stg, int ks) {
        const uint32_t cA = (uint32_t)(ks * 2 + matc);
#pragma unroll
        for (int mt = 0; mt < 2; mt++) {
            uint32_t ch = a_b8[mt] + ((a_hm[mt] | cA) ^ a_e[mt]);
            ldsm4(aF[mt], stg + ch * 16);
        }
        const uint32_t bbase = stg + (uint32_t)A_BYTES + (uint32_t)ks * 4096u;
#pragma unroll
        for (int ntp = 0; ntp < 4; ntp++) {
            uint32_t rr[4];
            ldsm4t(rr, bbase + b_cb[ntp]);
            bF[2 * ntp][0] = rr[0];     bF[2 * ntp][1] = rr[1];
            bF[2 * ntp + 1][0] = rr[2]; bF[2 * ntp + 1][1] = rr[3];
        }
    };
    auto mma_all = [&]() {
#pragma unroll
        for (int mt = 0; mt < 2; mt++)
#pragma unroll
            for (int nt = 0; nt < 8; nt++)
                mma16(acc[mt][nt], aF[mt], bF[nt]);
    };

    int istage = 5, cs = 0;
    for (int kp = 0; kp < KT; kp += 2) {
        const uint32_t stg0 = sbase + (uint32_t)cs * STG_BYTES;
        if (++cs == STAGES) cs = 0;
        const uint32_t stg1 = sbase + (uint32_t)cs * STG_BYTES;
        if (++cs == STAGES) cs = 0;

        CP_WAIT3();             // stages kp and kp+1 complete (oldest 2 of 5)
        __syncthreads();        // slots (kp+5)%7, (kp+6)%7 were consumed last pair -> safe

        load_frag(stg0, sw);    // ktile kp, group-order ks
        if (kp + 5 < KT) issue(sbase + (uint32_t)istage * STG_BYTES);
        CP_COMMIT();
        if (++istage == STAGES) istage = 0;
        if (kp + 6 < KT) issue(sbase + (uint32_t)istage * STG_BYTES);
        CP_COMMIT();
        if (++istage == STAGES) istage = 0;

        mma_all();              // ktile kp, first ks (group-dependent)
        load_frag(stg0, sw ^ 1);
        mma_all();              // ktile kp, second ks
        load_frag(stg1, sw);
        mma_all();              // ktile kp+1, first ks
        load_frag(stg1, sw ^ 1);
        mma_all();              // ktile kp+1, second ks
    }
    __syncthreads();

    // ---------------- epilogue ----------------
    __half* hpw = (__half*)g_hp4;
    __half* part = ((__half*)g_part16) + (size_t)e * ((size_t)B_ * DOUT_);
#pragma unroll
    for (int mt = 0; mt < 2; mt++) {
        const int r0 = m0 + wm * 32 + mt * 16 + g;   // rows r0, r0+8
        float p0 = 0.f, p1 = 0.f;
        if (MODE == 1) {
            p0 = g_probs[(size_t)r0 * NE_ + e];
            p1 = g_probs[(size_t)(r0 + 8) * NE_ + e];
        }
#pragma unroll
        for (int nt = 0; nt < 8; nt++) {
            const int c = wn * 64 + nt * 8 + 2 * t;
            if (MODE == 1) {
                float2 bv = *(const float2*)(bias + (size_t)e * DH_ + n0 + c);
                __half2 v0 = __floats2half2_rn(p0 * fmaxf(acc[mt][nt][0] + bv.x, 0.f),
                                               p0 * fmaxf(acc[mt][nt][1] + bv.y, 0.f));
                __half2 v1 = __floats2half2_rn(p1 * fmaxf(acc[mt][nt][2] + bv.x, 0.f),
                                               p1 * fmaxf(acc[mt][nt][3] + bv.y, 0.f));
                size_t base = (size_t)e * DH_ + n0 + c;
                *(__half2*)(hpw + (size_t)r0 * (NE_ * DH_) + base) = v0;
                *(__half2*)(hpw + (size_t)(r0 + 8) * (NE_ * DH_) + base) = v1;
            } else {
                *(__half2*)(part + (size_t)r0 * DOUT_ + n0 + c) =
                    __floats2half2_rn(acc[mt][nt][0], acc[mt][nt][1]);
                *(__half2*)(part + (size_t)(r0 + 8) * DOUT_ + n0 + c) =
                    __floats2half2_rn(acc[mt][nt][2], acc[mt][nt][3]);
            }
        }
    }
}

// ---------------- reduce: out = sum_q part16[q] + sum_e probs*b2 ----------------
__global__ __launch_bounds__(256) void reduce_kernel(const float* __restrict__ b2,
                                                     float* __restrict__ out) {
    const int b = blockIdx.x;
    const int c = threadIdx.x * 4;
    const __half* pp = (const __half*)g_part16;
    float p[NE_];
#pragma unroll
    for (int e = 0; e < NE_; e++) p[e] = g_probs[(size_t)b * NE_ + e];
    size_t off = (size_t)b * DOUT_ + c;
    float4 r = make_float4(0.f, 0.f, 0.f, 0.f);
#pragma unroll
    for (int q = 0; q < KSPLIT; q++) {
        const __half* pq = pp + (size_t)q * ((size_t)B_ * DOUT_) + off;
        __half2 h0 = *(const __half2*)(pq);
        __half2 h1 = *(const __half2*)(pq + 2);
        float2 f0 = __half22float2(h0), f1 = __half22float2(h1);
        r.x += f0.x; r.y += f0.y; r.z += f1.x; r.w += f1.y;
    }
#pragma unroll
    for (int e = 0; e < NE_; e++) {
        float4 bv = *(const float4*)(b2 + (size_t)e * DOUT_ + c);
        r.x += p[e] * bv.x; r.y += p[e] * bv.y;
        r.z += p[e] * bv.z; r.w += p[e] * bv.w;
    }
    *(float4*)(out + off) = r;
}

// ---------------- gating (+ x -> fp16 fold) / aux ----------------
__global__ void zero_kernel() {
    if (threadIdx.x < 16) g_sums[threadIdx.x] = 0.f;
}

// 8 warps x 2 rows = 16 rows per block; grid = B_/16 = 512
__global__ __launch_bounds__(256) void gate_kernel(const float* __restrict__ x,
                                                   const float* __restrict__ gum,
                                                   const float* __restrict__ gw,
                                                   const float* __restrict__ gb,
                                                   __half* __restrict__ xh) {
    __shared__ float psum[16];
    int tid = threadIdx.x;
    if (tid < 16) psum[tid] = 0.f;
    __syncthreads();
    int warp = tid >> 5, lane = tid & 31;
    int row0 = blockIdx.x * 16 + warp * 2;

    float acc0[NE_], acc1[NE_];
#pragma unroll
    for (int e = 0; e < NE_; e++) { acc0[e] = 0.f; acc1[e] = 0.f; }
    const float* xr0 = x + (size_t)row0 * DIN_;
    const float* xr1 = xr0 + DIN_;
    __half* xo0 = xh + (size_t)row0 * DIN_;
    __half* xo1 = xo0 + DIN_;
    for (int k = lane; k < DIN_; k += 32) {
        float xv0 = xr0[k], xv1 = xr1[k];
        xo0[k] = __float2half_rn(xv0);
        xo1[k] = __float2half_rn(xv1);
        float4 w0 = *(const float4*)(gw + (size_t)k * NE_);
        float4 w1v = *(const float4*)(gw + (size_t)k * NE_ + 4);
        acc0[0] += xv0 * w0.x;  acc0[1] += xv0 * w0.y;
        acc0[2] += xv0 * w0.z;  acc0[3] += xv0 * w0.w;
        acc0[4] += xv0 * w1v.x; acc0[5] += xv0 * w1v.y;
        acc0[6] += xv0 * w1v.z; acc0[7] += xv0 * w1v.w;
        acc1[0] += xv1 * w0.x;  acc1[1] += xv1 * w0.y;
        acc1[2] += xv1 * w0.z;  acc1[3] += xv1 * w0.w;
        acc1[4] += xv1 * w1v.x; acc1[5] += xv1 * w1v.y;
        acc1[6] += xv1 * w1v.z; acc1[7] += xv1 * w1v.w;
    }
#pragma unroll
    for (int e = 0; e < NE_; e++) {
#pragma unroll
        for (int off = 16; off > 0; off >>= 1) {
            acc0[e] += __shfl_xor_sync(0xffffffffu, acc0[e], off);
            acc1[e] += __shfl_xor_sync(0xffffffffu, acc1[e], off);
        }
    }
    if (lane < 2) {
        int row = row0 + lane;
        float* accp = (lane == 0) ? acc0 : acc1;
        float s1[NE_], s2[NE_];
        float m1 = -1e30f, m2 = -1e30f;
#pragma unroll
        for (int e = 0; e < NE_; e++) {
            float lg = accp[e] + gb[e];
            s1[e] = (lg + gum[(size_t)row * NE_ + e]) * (1.0f / TAU_);
            s2[e] = lg * (1.0f / TAU_);
            m1 = fmaxf(m1, s1[e]); m2 = fmaxf(m2, s2[e]);
        }
        float d1 = 0.f, d2 = 0.f;
#pragma unroll
        for (int e = 0; e < NE_; e++) {
            s1[e] = expf(s1[e] - m1); s2[e] = expf(s2[e] - m2);
            d1 += s1[e]; d2 += s2[e];
        }
#pragma unroll
        for (int e = 0; e < NE_; e++) {
            float p = s1[e] / d1, r = s2[e] / d2;
            g_probs[(size_t)row * NE_ + e] = p;
            atomicAdd(&psum[e], p);
            atomicAdd(&psum[8 + e], r);
        }
    }
    __syncthreads();
    if (tid < 16) atomicAdd(&g_sums[tid], psum[tid]);
}

__global__ void aux_kernel(float* __restrict__ out, int out_size) {
    if (threadIdx.x != 0 || blockIdx.x != 0) return;
    float ld[NE_], imp[NE_];
    float sl = 0.f, si = 0.f;
#pragma unroll
    for (int e = 0; e < NE_; e++) {
        ld[e]  = g_sums[e] / (float)B_;
        imp[e] = g_sums[8 + e] / (float)B_;
        sl += ld[e]; si += imp[e];
    }
    float ml = sl / (float)NE_, mi = si / (float)NE_;
    float vl = 0.f, vi = 0.f, sw = 0.f;
#pragma unroll
    for (int e = 0; e < NE_; e++) {
        vl += (ld[e] - ml) * (ld[e] - ml);
        vi += (imp[e] - mi) * (imp[e] - mi);
        sw += imp[e] * ld[e];
    }
    float cvl = sqrtf(vl / (float)(NE_ - 1)) / (ml + 1e-8f);
    float cvi = sqrtf(vi / (float)(NE_ - 1)) / (mi + 1e-8f);
    out[out_size - 1] = ((float)NE_ * sw + cvi + cvl) * LAMB_;
}

// ---------------- launch ----------------
extern "C" void kernel_launch(void* const* d_in, const int* in_sizes, int n_in,
                              void* d_out, int out_size) {
    const float* x   = (const float*)d_in[0];
    const float* gum = (const float*)d_in[1];
    const float* gw  = (const float*)d_in[2];
    const float* gb  = (const float*)d_in[3];
    const float* w1  = (const float*)d_in[4];
    const float* b1  = (const float*)d_in[5];
    const float* w2  = (const float*)d_in[6];
    const float* b2  = (const float*)d_in[7];
    float* out = (float*)d_out;

    __half *xh = nullptr, *w1h = nullptr, *w2h = nullptr;
    cudaGetSymbolAddress((void**)&xh,  g_xh4);
    cudaGetSymbolAddress((void**)&w1h, g_w1h4);
    cudaGetSymbolAddress((void**)&w2h, g_w2h4);

    cudaFuncSetAttribute((const void*)gemm_h<1>,
                         cudaFuncAttributeMaxDynamicSharedMemorySize, SMEM_BYTES);
    cudaFuncSetAttribute((const void*)gemm_h<2>,
                         cudaFuncAttributeMaxDynamicSharedMemorySize, SMEM_BYTES);

    zero_kernel<<<1, 32>>>();
    half_kernel<<<2048, 256>>>(w1, w1h, (NE_ * DIN_ * DH_) / 4,
                               w2, w2h, (NE_ * DH_ * DOUT_) / 4);
    gate_kernel<<<B_ / 16, 256>>>(x, gum, gw, gb, xh);
    gemm_h<1><<<dim3(DH_ / BN, B_ / BM, NE_), NT, SMEM_BYTES>>>(xh, w1h, b1);
    gemm_h<2><<<dim3(DOUT_ / BN, B_ / BM, KSPLIT), NT, SMEM_BYTES>>>(nullptr, w2h, nullptr);
    reduce_kernel<<<B_, 256>>>(b2, out);
    aux_kernel<<<1, 1>>>(out, out_size);
}

// round 15
// speedup vs baseline: 1.0596x; 1.0596x over previous
#include <cuda_runtime.h>
#include <cuda_fp16.h>
#include <cstdint>
#include <math.h>

#define B_    8192
#define DIN_  1024
#define DH_   2048
#define DOUT_ 1024
#define NE_   8
#define TAU_  0.8f
#define LAMB_ 0.05f

// block 128x128, 8 warps (4x2), warp tile 32x64, BK=32 halves, 7 stages, 2 CTAs/SM
// ktiles processed in PAIRS: one wait+sync per 2 ktiles. Fixed ks order (compile-time).
#define BM 128
#define BN 128
#define BK 32
#define NT 256
#define STAGES 7
#define A_BYTES (BM * BK * 2)         // 8192
#define B_BYTES (BK * BN * 2)         // 8192
#define STG_BYTES (A_BYTES + B_BYTES) // 16384
#define SMEM_BYTES (STAGES * STG_BYTES)  // 114688
#define KSPLIT 4

// -------- scratch (__device__ globals; 16B-aligned via uint4) --------
__device__ float g_probs[(size_t)B_ * NE_];
__device__ float g_sums[16];
__device__ uint4 g_xh4[(size_t)B_ * DIN_ / 8];
__device__ uint4 g_w1h4[(size_t)NE_ * DIN_ * DH_ / 8];
__device__ uint4 g_w2h4[(size_t)NE_ * DH_ * DOUT_ / 8];
__device__ uint4 g_hp4[(size_t)B_ * NE_ * DH_ / 8];         // fp16 h' [B][E*Dh]
__device__ uint4 g_part16[(size_t)KSPLIT * B_ * DOUT_ / 8]; // fp16 split-K partials

// ---------------- helpers ----------------
__device__ __forceinline__ uint32_t smem_u32(const void* p) {
    uint32_t a;
    asm("{ .reg .u64 t; cvta.to.shared.u64 t, %1; cvt.u32.u64 %0, t; }" : "=r"(a) : "l"(p));
    return a;
}
__device__ __forceinline__ void cpa16(uint32_t dst, const void* src) {
    asm volatile("cp.async.cg.shared.global [%0], [%1], 16;" :: "r"(dst), "l"(src));
}
#define CP_COMMIT() asm volatile("cp.async.commit_group;" ::: "memory")
#define CP_WAIT3()  asm volatile("cp.async.wait_group 3;" ::: "memory")

__device__ __forceinline__ void ldsm4(uint32_t* r, uint32_t addr) {
    asm volatile("ldmatrix.sync.aligned.m8n8.x4.shared.b16 {%0,%1,%2,%3}, [%4];"
        : "=r"(r[0]), "=r"(r[1]), "=r"(r[2]), "=r"(r[3]) : "r"(addr));
}
__device__ __forceinline__ void ldsm4t(uint32_t* r, uint32_t addr) {
    asm volatile("ldmatrix.sync.aligned.m8n8.x4.trans.shared.b16 {%0,%1,%2,%3}, [%4];"
        : "=r"(r[0]), "=r"(r[1]), "=r"(r[2]), "=r"(r[3]) : "r"(addr));
}
__device__ __forceinline__ void mma16(float* c, const uint32_t* a, const uint32_t* b) {
    asm volatile(
        "mma.sync.aligned.m16n8k16.row.col.f32.f16.f16.f32 "
        "{%0,%1,%2,%3},{%4,%5,%6,%7},{%8,%9},{%0,%1,%2,%3};"
        : "+f"(c[0]), "+f"(c[1]), "+f"(c[2]), "+f"(c[3])
        : "r"(a[0]), "r"(a[1]), "r"(a[2]), "r"(a[3]), "r"(b[0]), "r"(b[1]));
}

// ---------------- prep: fp32 -> fp16 (w1, w2; x handled in gate) ----------------
__global__ __launch_bounds__(256) void half_kernel(const float* __restrict__ s1,
                                                   __half* __restrict__ d1, int n1_,
                                                   const float* __restrict__ s2,
                                                   __half* __restrict__ d2, int n2_) {
    int stride = gridDim.x * 256;
    int t0 = blockIdx.x * 256 + threadIdx.x;
    for (int i = t0; i < n1_; i += stride) {
        float4 v = ((const float4*)s1)[i];
        ((__half2*)d1)[2 * i]     = __floats2half2_rn(v.x, v.y);
        ((__half2*)d1)[2 * i + 1] = __floats2half2_rn(v.z, v.w);
    }
    for (int i = t0; i < n2_; i += stride) {
        float4 v = ((const float4*)s2)[i];
        ((__half2*)d2)[2 * i]     = __floats2half2_rn(v.x, v.y);
        ((__half2*)d2)[2 * i + 1] = __floats2half2_rn(v.z, v.w);
    }
}

// ---------------- main GEMM (fp16 in, fp32 accum), 256 threads, 2 CTAs/SM ----------------
// MODE 1: h' = fp16(probs * relu(xh @ w1h + b1)), grid.z = expert, KT=32
// MODE 2: part16[kq] = fp16(hp slice @ w2h slice), grid.z = kq, KT=128
template <int MODE>
__global__ __launch_bounds__(NT, 2) void gemm_h(const __half* __restrict__ Aglob,
                                                const __half* __restrict__ Bglob,
                                                const float* __restrict__ bias) {
    constexpr int KT  = (MODE == 1) ? (DIN_ / BK) : (NE_ * DH_ / BK / KSPLIT);
    constexpr int LDA = (MODE == 1) ? DIN_ : (NE_ * DH_);
    constexpr int LDB = (MODE == 1) ? DH_ : DOUT_;

    extern __shared__ float sm[];
    const int tid  = threadIdx.x;
    const int lane = tid & 31, warp = tid >> 5;
    const int g = lane >> 2, t = lane & 3;
    const int wm = warp >> 1, wn = warp & 1;     // 4x2 warps, warp tile 32x64

    const int e  = blockIdx.z;                   // expert (MODE1) or kq (MODE2)
    const int m0 = blockIdx.y * BM;
    const int n0 = blockIdx.x * BN;
    const __half* hp = (const __half*)g_hp4;
    const __half* Ap = (MODE == 1) ? (Aglob + (size_t)m0 * LDA)
                                   : (hp + (size_t)m0 * LDA + (size_t)e * (NE_ * DH_ / KSPLIT));
    const __half* Bp = (MODE == 1)
        ? (Bglob + (size_t)e * DIN_ * DH_ + n0)
        : (Bglob + (size_t)e * (NE_ * DH_ / KSPLIT) * LDB + n0);
    const uint32_t sbase = smem_u32(sm);

    // copy descriptors: A 512 chunks (2/thr), B 512 chunks (2/thr)
    const __half* pA[2]; uint32_t soA[2];
    const __half* pB[2]; uint32_t soB[2];
#pragma unroll
    for (int j = 0; j < 2; j++) {
        int id = tid + j * NT, m = id >> 2, c = id & 3;
        pA[j]  = Ap + (size_t)m * LDA + c * 8;
        soA[j] = (uint32_t)(((m >> 1) << 3) + ((((m & 1) << 2) | c) ^ ((m >> 1) & 7))) * 16;
    }
#pragma unroll
    for (int j = 0; j < 2; j++) {
        int id = tid + j * NT, k = id >> 4, cn = id & 15;
        pB[j]  = Bp + (size_t)k * LDB + cn * 8;
        soB[j] = (uint32_t)(A_BYTES) + (uint32_t)(k * 16 + (cn ^ (k & 7))) * 16;
    }

    auto issue = [&](uint32_t stg) {
#pragma unroll
        for (int j = 0; j < 2; j++) { cpa16(stg + soA[j], pA[j]); pA[j] += BK; }
#pragma unroll
        for (int j = 0; j < 2; j++) { cpa16(stg + soB[j], pB[j]); pB[j] += (size_t)BK * LDB; }
    };

    float acc[2][8][4];
#pragma unroll
    for (int a = 0; a < 2; a++)
#pragma unroll
        for (int b = 0; b < 8; b++)
#pragma unroll
            for (int c = 0; c < 4; c++) acc[a][b][c] = 0.f;

    // prologue: 5 stages in flight
#pragma unroll
    for (int p = 0; p < 5; p++) { issue(sbase + p * STG_BYTES); CP_COMMIT(); }

    // ldmatrix per-lane precomputes
    const int mat = lane >> 3, mr = lane & 7;
    const int matc = mat >> 1, matm = (mat & 1) << 3;
    uint32_t a_b8[2], a_e[2], a_hm[2];
#pragma unroll
    for (int mt = 0; mt < 2; mt++) {
        int m = wm * 32 + mt * 16 + matm + mr;
        a_b8[mt] = (uint32_t)((m >> 1) << 3);
        a_e[mt]  = (uint32_t)((m >> 1) & 7);
        a_hm[mt] = (uint32_t)((m & 1) << 2);
    }
    uint32_t b_cb[4];
#pragma unroll
    for (int ntp = 0; ntp < 4; ntp++) {
        int kb = matm + mr;                    // row within 16-row half-tile
        int cn = wn * 8 + ntp * 2 + matc;      // chunk-in-row
        b_cb[ntp] = (uint32_t)(kb * 16 + (cn ^ mr)) * 16;
    }

    uint32_t aF[2][4], bF[8][2];
    auto load_frag = [&](uint32_t stg, int ks) {
        const uint32_t cA = (uint32_t)(ks * 2 + matc);
#pragma unroll
        for (int mt = 0; mt < 2; mt++) {
            uint32_t ch = a_b8[mt] + ((a_hm[mt] | cA) ^ a_e[mt]);
            ldsm4(aF[mt], stg + ch * 16);
        }
        const uint32_t bbase = stg + (uint32_t)A_BYTES + (uint32_t)ks * 4096u;
#pragma unroll
        for (int ntp = 0; ntp < 4; ntp++) {
            uint32_t rr[4];
            ldsm4t(rr, bbase + b_cb[ntp]);
            bF[2 * ntp][0] = rr[0];     bF[2 * ntp][1] = rr[1];
            bF[2 * ntp + 1][0] = rr[2]; bF[2 * ntp + 1][1] = rr[3];
        }
    };
    auto mma_all = [&]() {
#pragma unroll
        for (int mt = 0; mt < 2; mt++)
#pragma unroll
            for (int nt = 0; nt < 8; nt++)
                mma16(acc[mt][nt], aF[mt], bF[nt]);
    };

    int istage = 5, cs = 0;
    for (int kp = 0; kp < KT; kp += 2) {
        const uint32_t stg0 = sbase + (uint32_t)cs * STG_BYTES;
        if (++cs == STAGES) cs = 0;
        const uint32_t stg1 = sbase + (uint32_t)cs * STG_BYTES;
        if (++cs == STAGES) cs = 0;

        CP_WAIT3();             // stages kp and kp+1 complete (oldest 2 of 5)
        __syncthreads();        // slots (kp+5)%7, (kp+6)%7 were consumed last pair -> safe

        load_frag(stg0, 0);     // ktile kp, ks0 frags first
        if (kp + 5 < KT) issue(sbase + (uint32_t)istage * STG_BYTES);
        CP_COMMIT();
        if (++istage == STAGES) istage = 0;
        if (kp + 6 < KT) issue(sbase + (uint32_t)istage * STG_BYTES);
        CP_COMMIT();
        if (++istage == STAGES) istage = 0;

        mma_all();              // ktile kp ks0
        load_frag(stg0, 1);
        mma_all();              // ktile kp ks1
        load_frag(stg1, 0);
        mma_all();              // ktile kp+1 ks0
        load_frag(stg1, 1);
        mma_all();              // ktile kp+1 ks1
    }
    __syncthreads();

    // ---------------- epilogue ----------------
    __half* hpw = (__half*)g_hp4;
    __half* part = ((__half*)g_part16) + (size_t)e * ((size_t)B_ * DOUT_);
#pragma unroll
    for (int mt = 0; mt < 2; mt++) {
        const int r0 = m0 + wm * 32 + mt * 16 + g;   // rows r0, r0+8
        float p0 = 0.f, p1 = 0.f;
        if (MODE == 1) {
            p0 = g_probs[(size_t)r0 * NE_ + e];
            p1 = g_probs[(size_t)(r0 + 8) * NE_ + e];
        }
#pragma unroll
        for (int nt = 0; nt < 8; nt++) {
            const int c = wn * 64 + nt * 8 + 2 * t;
            if (MODE == 1) {
                float2 bv = *(const float2*)(bias + (size_t)e * DH_ + n0 + c);
                __half2 v0 = __floats2half2_rn(p0 * fmaxf(acc[mt][nt][0] + bv.x, 0.f),
                                               p0 * fmaxf(acc[mt][nt][1] + bv.y, 0.f));
                __half2 v1 = __floats2half2_rn(p1 * fmaxf(acc[mt][nt][2] + bv.x, 0.f),
                                               p1 * fmaxf(acc[mt][nt][3] + bv.y, 0.f));
                size_t base = (size_t)e * DH_ + n0 + c;
                *(__half2*)(hpw + (size_t)r0 * (NE_ * DH_) + base) = v0;
                *(__half2*)(hpw + (size_t)(r0 + 8) * (NE_ * DH_) + base) = v1;
            } else {
                *(__half2*)(part + (size_t)r0 * DOUT_ + n0 + c) =
                    __floats2half2_rn(acc[mt][nt][0], acc[mt][nt][1]);
                *(__half2*)(part + (size_t)(r0 + 8) * DOUT_ + n0 + c) =
                    __floats2half2_rn(acc[mt][nt][2], acc[mt][nt][3]);
            }
        }
    }
}

// ---------------- reduce: out = sum_q part16[q] + sum_e probs*b2 ----------------
__global__ __launch_bounds__(256) void reduce_kernel(const float* __restrict__ b2,
                                                     float* __restrict__ out) {
    const int b = blockIdx.x;
    const int c = threadIdx.x * 4;
    const __half* pp = (const __half*)g_part16;
    float p[NE_];
#pragma unroll
    for (int e = 0; e < NE_; e++) p[e] = g_probs[(size_t)b * NE_ + e];
    size_t off = (size_t)b * DOUT_ + c;
    float4 r = make_float4(0.f, 0.f, 0.f, 0.f);
#pragma unroll
    for (int q = 0; q < KSPLIT; q++) {
        const __half* pq = pp + (size_t)q * ((size_t)B_ * DOUT_) + off;
        __half2 h0 = *(const __half2*)(pq);
        __half2 h1 = *(const __half2*)(pq + 2);
        float2 f0 = __half22float2(h0), f1 = __half22float2(h1);
        r.x += f0.x; r.y += f0.y; r.z += f1.x; r.w += f1.y;
    }
#pragma unroll
    for (int e = 0; e < NE_; e++) {
        float4 bv = *(const float4*)(b2 + (size_t)e * DOUT_ + c);
        r.x += p[e] * bv.x; r.y += p[e] * bv.y;
        r.z += p[e] * bv.z; r.w += p[e] * bv.w;
    }
    *(float4*)(out + off) = r;
}

// ---------------- gating (+ x -> fp16 fold) / aux ----------------
__global__ void zero_kernel() {
    if (threadIdx.x < 16) g_sums[threadIdx.x] = 0.f;
}

// 8 warps x 2 rows = 16 rows per block; grid = B_/16 = 512
__global__ __launch_bounds__(256) void gate_kernel(const float* __restrict__ x,
                                                   const float* __restrict__ gum,
                                                   const float* __restrict__ gw,
                                                   const float* __restrict__ gb,
                                                   __half* __restrict__ xh) {
    __shared__ float psum[16];
    int tid = threadIdx.x;
    if (tid < 16) psum[tid] = 0.f;
    __syncthreads();
    int warp = tid >> 5, lane = tid & 31;
    int row0 = blockIdx.x * 16 + warp * 2;

    float acc0[NE_], acc1[NE_];
#pragma unroll
    for (int e = 0; e < NE_; e++) { acc0[e] = 0.f; acc1[e] = 0.f; }
    const float* xr0 = x + (size_t)row0 * DIN_;
    const float* xr1 = xr0 + DIN_;
    __half* xo0 = xh + (size_t)row0 * DIN_;
    __half* xo1 = xo0 + DIN_;
    for (int k = lane; k < DIN_; k += 32) {
        float xv0 = xr0[k], xv1 = xr1[k];
        xo0[k] = __float2half_rn(xv0);
        xo1[k] = __float2half_rn(xv1);
        float4 w0 = *(const float4*)(gw + (size_t)k * NE_);
        float4 w1v = *(const float4*)(gw + (size_t)k * NE_ + 4);
        acc0[0] += xv0 * w0.x;  acc0[1] += xv0 * w0.y;
        acc0[2] += xv0 * w0.z;  acc0[3] += xv0 * w0.w;
        acc0[4] += xv0 * w1v.x; acc0[5] += xv0 * w1v.y;
        acc0[6] += xv0 * w1v.z; acc0[7] += xv0 * w1v.w;
        acc1[0] += xv1 * w0.x;  acc1[1] += xv1 * w0.y;
        acc1[2] += xv1 * w0.z;  acc1[3] += xv1 * w0.w;
        acc1[4] += xv1 * w1v.x; acc1[5] += xv1 * w1v.y;
        acc1[6] += xv1 * w1v.z; acc1[7] += xv1 * w1v.w;
    }
#pragma unroll
    for (int e = 0; e < NE_; e++) {
#pragma unroll
        for (int off = 16; off > 0; off >>= 1) {
            acc0[e] += __shfl_xor_sync(0xffffffffu, acc0[e], off);
            acc1[e] += __shfl_xor_sync(0xffffffffu, acc1[e], off);
        }
    }
    if (lane < 2) {
        int row = row0 + lane;
        float* accp = (lane == 0) ? acc0 : acc1;
        float s1[NE_], s2[NE_];
        float m1 = -1e30f, m2 = -1e30f;
#pragma unroll
        for (int e = 0; e < NE_; e++) {
            float lg = accp[e] + gb[e];
            s1[e] = (lg + gum[(size_t)row * NE_ + e]) * (1.0f / TAU_);
            s2[e] = lg * (1.0f / TAU_);
            m1 = fmaxf(m1, s1[e]); m2 = fmaxf(m2, s2[e]);
        }
        float d1 = 0.f, d2 = 0.f;
#pragma unroll
        for (int e = 0; e < NE_; e++) {
            s1[e] = expf(s1[e] - m1); s2[e] = expf(s2[e] - m2);
            d1 += s1[e]; d2 += s2[e];
        }
#pragma unroll
        for (int e = 0; e < NE_; e++) {
            float p = s1[e] / d1, r = s2[e] / d2;
            g_probs[(size_t)row * NE_ + e] = p;
            atomicAdd(&psum[e], p);
            atomicAdd(&psum[8 + e], r);
        }
    }
    __syncthreads();
    if (tid < 16) atomicAdd(&g_sums[tid], psum[tid]);
}

__global__ void aux_kernel(float* __restrict__ out, int out_size) {
    if (threadIdx.x != 0 || blockIdx.x != 0) return;
    float ld[NE_], imp[NE_];
    float sl = 0.f, si = 0.f;
#pragma unroll
    for (int e = 0; e < NE_; e++) {
        ld[e]  = g_sums[e] / (float)B_;
        imp[e] = g_sums[8 + e] / (float)B_;
        sl += ld[e]; si += imp[e];
    }
    float ml = sl / (float)NE_, mi = si / (float)NE_;
    float vl = 0.f, vi = 0.f, sw = 0.f;
#pragma unroll
    for (int e = 0; e < NE_; e++) {
        vl += (ld[e] - ml) * (ld[e] - ml);
        vi += (imp[e] - mi) * (imp[e] - mi);
        sw += imp[e] * ld[e];
    }
    float cvl = sqrtf(vl / (float)(NE_ - 1)) / (ml + 1e-8f);
    float cvi = sqrtf(vi / (float)(NE_ - 1)) / (mi + 1e-8f);
    out[out_size - 1] = ((float)NE_ * sw + cvi + cvl) * LAMB_;
}

// ---------------- launch ----------------
extern "C" void kernel_launch(void* const* d_in, const int* in_sizes, int n_in,
                              void* d_out, int out_size) {
    const float* x   = (const float*)d_in[0];
    const float* gum = (const float*)d_in[1];
    const float* gw  = (const float*)d_in[2];
    const float* gb  = (const float*)d_in[3];
    const float* w1  = (const float*)d_in[4];
    const float* b1  = (const float*)d_in[5];
    const float* w2  = (const float*)d_in[6];
    const float* b2  = (const float*)d_in[7];
    float* out = (float*)d_out;

    __half *xh = nullptr, *w1h = nullptr, *w2h = nullptr;
    cudaGetSymbolAddress((void**)&xh,  g_xh4);
    cudaGetSymbolAddress((void**)&w1h, g_w1h4);
    cudaGetSymbolAddress((void**)&w2h, g_w2h4);

    cudaFuncSetAttribute((const void*)gemm_h<1>,
                         cudaFuncAttributeMaxDynamicSharedMemorySize, SMEM_BYTES);
    cudaFuncSetAttribute((const void*)gemm_h<2>,
                         cudaFuncAttributeMaxDynamicSharedMemorySize, SMEM_BYTES);

    zero_kernel<<<1, 32>>>();
    half_kernel<<<2048, 256>>>(w1, w1h, (NE_ * DIN_ * DH_) / 4,
                               w2, w2h, (NE_ * DH_ * DOUT_) / 4);
    gate_kernel<<<B_ / 16, 256>>>(x, gum, gw, gb, xh);
    gemm_h<1><<<dim3(DH_ / BN, B_ / BM, NE_), NT, SMEM_BYTES>>>(xh, w1h, b1);
    gemm_h<2><<<dim3(DOUT_ / BN, B_ / BM, KSPLIT), NT, SMEM_BYTES>>>(nullptr, w2h, nullptr);
    reduce_kernel<<<B_, 256>>>(b2, out);
    aux_kernel<<<1, 1>>>(out, out_size);
}